// round 16
// baseline (speedup 1.0000x reference)
#include <cuda_runtime.h>
#include <cuda_fp16.h>
#include <math.h>
#include <stdint.h>

#define B_  256
#define T_  256
#define I_  64
#define H_  2048
#define L_  4
#define BH_ (B_ * H_)
#define K2_ 4096

// ---- wave kernel tiling: CTA tile 128x128, K chunk 64 (fp16), 3 stages ----
#define CHUNK    64
#define PITCH    72                      // fp16 elems per smem row (144B)
#define TILE_E   (128 * PITCH)           // one operand plane (elems)
#define STAGE_E  (4 * TILE_E)            // Ah, Al, Bh, Bl planes
#define NSTAGE   3
#define DYN_SMEM (NSTAGE * STAGE_E * 2)  // 221184 bytes
#define WTHREADS 512
#define NCTA     148
#define RSCALE   1024.f
#define INV_RS   (1.f / 1024.f)

#define MODE_NONE 0
#define MODE_OWN  1                      // layer 1-3 tile owner (q0-2, waits for q3)
#define MODE_L0   2                      // layer-0 tile (full K, immediate epilogue)
#define MODE_HELP 3                      // quarter-3 / eighth helper (writes partial)

// ---- device scratch (allocation-free contract) ----
__device__ float g_XT[(size_t)T_ * B_ * I_];
__device__ float g_XP[(size_t)T_ * B_ * H_];
__device__ __half g_W0h[(size_t)H_ * H_];
__device__ __half g_W0l[(size_t)H_ * H_];
__device__ __half g_Wch[(size_t)3 * H_ * K2_];
__device__ __half g_Wcl[(size_t)3 * H_ * K2_];
__device__ __half g_Hh[(size_t)L_ * 2 * BH_];
__device__ __half g_Hl[(size_t)L_ * 2 * BH_];
__device__ float g_PART[96][128 * 128];      // quarter-3 partials (fp32, merged)
__device__ float g_PART2[4][128 * 128];      // second eighth of tiles q=92..95
__device__ unsigned g_flag[96];              // per-tile contributor counters
__device__ unsigned g_bar;

// ---------------------------------------------------------------------------
// helpers
// ---------------------------------------------------------------------------
__device__ __forceinline__ unsigned sptr(const void* p) {
    return (unsigned)__cvta_generic_to_shared(p);
}
__device__ __forceinline__ void cp16(__half* s, const __half* g) {
    asm volatile("cp.async.cg.shared.global [%0], [%1], 16;" :: "r"(sptr(s)), "l"(g));
}
__device__ __forceinline__ void ldsm4(unsigned& r0, unsigned& r1, unsigned& r2,
                                      unsigned& r3, const __half* p) {
    asm volatile("ldmatrix.sync.aligned.m8n8.x4.shared.b16 {%0,%1,%2,%3}, [%4];"
                 : "=r"(r0), "=r"(r1), "=r"(r2), "=r"(r3) : "r"(sptr(p)));
}
__device__ __forceinline__ void mma_f32acc(float* d, const unsigned* a, const unsigned* b) {
    asm volatile("mma.sync.aligned.m16n8k16.row.col.f32.f16.f16.f32 "
                 "{%0,%1,%2,%3}, {%4,%5,%6,%7}, {%8,%9}, {%0,%1,%2,%3};"
                 : "+f"(d[0]), "+f"(d[1]), "+f"(d[2]), "+f"(d[3])
                 : "r"(a[0]), "r"(a[1]), "r"(a[2]), "r"(a[3]), "r"(b[0]), "r"(b[1]));
}
__device__ __forceinline__ void mma_f16acc(unsigned* d, const unsigned* a, const unsigned* b) {
    asm volatile("mma.sync.aligned.m16n8k16.row.col.f16.f16.f16.f16 "
                 "{%0,%1}, {%2,%3,%4,%5}, {%6,%7}, {%0,%1};"
                 : "+r"(d[0]), "+r"(d[1])
                 : "r"(a[0]), "r"(a[1]), "r"(a[2]), "r"(a[3]), "r"(b[0]), "r"(b[1]));
}
__device__ __forceinline__ void mbar_init(unsigned mbar, unsigned cnt) {
    asm volatile("mbarrier.init.shared.b64 [%0], %1;" :: "r"(mbar), "r"(cnt) : "memory");
}
__device__ __forceinline__ void mbar_arrive(unsigned mbar) {
    asm volatile("mbarrier.arrive.shared.b64 _, [%0];" :: "r"(mbar) : "memory");
}
__device__ __forceinline__ void cp_arrive_noinc(unsigned mbar) {
    asm volatile("cp.async.mbarrier.arrive.noinc.shared.b64 [%0];" :: "r"(mbar) : "memory");
}
__device__ __forceinline__ void mbar_wait(unsigned mbar, unsigned phase) {
    asm volatile(
        "{\n\t.reg .pred P1;\n\t"
        "WAIT_LOOP_%=:\n\t"
        "mbarrier.try_wait.parity.shared.b64 P1, [%0], %1;\n\t"
        "@P1 bra.uni WAIT_DONE_%=;\n\t"
        "bra.uni WAIT_LOOP_%=;\n\t"
        "WAIT_DONE_%=:\n\t}"
        :: "r"(mbar), "r"(phase) : "memory");
}

// ---------------------------------------------------------------------------
// x[B,T,I] -> XT[T,B,I]
// ---------------------------------------------------------------------------
__global__ void transpose_x(const float* __restrict__ x, float* __restrict__ xt) {
    int idx = blockIdx.x * blockDim.x + threadIdx.x;
    int i4 = idx & 15;
    int b  = (idx >> 4) & (B_ - 1);
    int t  = idx >> 12;
    float4 v = *(const float4*)(x + ((size_t)b * T_ + t) * I_ + i4 * 4);
    *(float4*)(xt + ((size_t)t * B_ + b) * I_ + i4 * 4) = v;
}

// ---------------------------------------------------------------------------
// fp32 NT GEMM (layer-0 input projection, K=64): C = A@W^T + bias
// ---------------------------------------------------------------------------
template<int BM, int BN, int BK, int TM, int TN>
__global__ __launch_bounds__((BM / TM) * (BN / TN))
void gemm_nt(const float* __restrict__ A, const float* __restrict__ W,
             const float* __restrict__ bias, float* __restrict__ C,
             int M, int N, int K)
{
    constexpr int NT  = (BM / TM) * (BN / TN);
    constexpr int KV  = BK / 4;
    constexpr int AV  = (BM * BK) / (NT * 4);
    constexpr int BV  = (BN * BK) / (NT * 4);
    constexpr int ARS = NT / KV;

    __shared__ __align__(16) float As[BK][BM + 4];
    __shared__ __align__(16) float Bs[BK][BN + 4];

    const int tid = threadIdx.x;
    const int bm  = blockIdx.y * BM;
    const int bn  = blockIdx.x * BN;
    const int lr = tid / KV;
    const int lc = (tid % KV) * 4;
    const float* Ag = A + (size_t)(bm + lr) * K + lc;
    const float* Wg = W + (size_t)(bn + lr) * K + lc;
    const int tx = tid % (BN / TN);
    const int ty = tid / (BN / TN);

    float acc[TM][TN];
    #pragma unroll
    for (int i = 0; i < TM; i++)
        #pragma unroll
        for (int j = 0; j < TN; j++) acc[i][j] = 0.f;

    float4 ra[AV], rb[BV];
    #pragma unroll
    for (int v = 0; v < AV; v++) ra[v] = *(const float4*)(Ag + (size_t)v * ARS * K);
    #pragma unroll
    for (int v = 0; v < BV; v++) rb[v] = *(const float4*)(Wg + (size_t)v * ARS * K);

    for (int k0 = 0; k0 < K; k0 += BK) {
        __syncthreads();
        #pragma unroll
        for (int v = 0; v < AV; v++) {
            As[lc + 0][lr + v * ARS] = ra[v].x; As[lc + 1][lr + v * ARS] = ra[v].y;
            As[lc + 2][lr + v * ARS] = ra[v].z; As[lc + 3][lr + v * ARS] = ra[v].w;
        }
        #pragma unroll
        for (int v = 0; v < BV; v++) {
            Bs[lc + 0][lr + v * ARS] = rb[v].x; Bs[lc + 1][lr + v * ARS] = rb[v].y;
            Bs[lc + 2][lr + v * ARS] = rb[v].z; Bs[lc + 3][lr + v * ARS] = rb[v].w;
        }
        __syncthreads();
        if (k0 + BK < K) {
            #pragma unroll
            for (int v = 0; v < AV; v++) ra[v] = *(const float4*)(Ag + (size_t)v * ARS * K + k0 + BK);
            #pragma unroll
            for (int v = 0; v < BV; v++) rb[v] = *(const float4*)(Wg + (size_t)v * ARS * K + k0 + BK);
        }
        #pragma unroll
        for (int kk = 0; kk < BK; ++kk) {
            float a[TM], b[TN];
            #pragma unroll
            for (int i = 0; i < TM; i += 4) *(float4*)&a[i] = *(const float4*)&As[kk][ty * TM + i];
            #pragma unroll
            for (int j = 0; j < TN; j += 4) *(float4*)&b[j] = *(const float4*)&Bs[kk][tx * TN + j];
            #pragma unroll
            for (int i = 0; i < TM; i++)
                #pragma unroll
                for (int j = 0; j < TN; j++) acc[i][j] = fmaf(a[i], b[j], acc[i][j]);
        }
    }
    const int n0 = bn + tx * TN;
    float4 bia = *(const float4*)(bias + n0);
    #pragma unroll
    for (int i = 0; i < TM; i++) {
        const size_t row = (size_t)(bm + ty * TM + i) * N + n0;
        float4 v;
        v.x = acc[i][0] + bia.x; v.y = acc[i][1] + bia.y;
        v.z = acc[i][2] + bia.z; v.w = acc[i][3] + bia.w;
        *(float4*)(C + row) = v;
    }
}

// ---------------------------------------------------------------------------
// weight precompute (merged): fp32 -> fp16 hi + scaled fp16 lo
// ---------------------------------------------------------------------------
__global__ void prep_weights(const float* __restrict__ Whh, const float* __restrict__ Wihr,
                             __half* __restrict__ w0h, __half* __restrict__ w0l,
                             __half* __restrict__ wch, __half* __restrict__ wcl)
{
    const size_t HH = (size_t)H_ * H_;
    size_t i = (size_t)blockIdx.x * blockDim.x + threadIdx.x;
    if (i < HH) {
        float v = Whh[i];
        __half a = __float2half(v);
        w0h[i] = a;
        w0l[i] = __float2half((v - __half2float(a)) * RSCALE);
    } else {
        size_t j = i - HH;
        const size_t per = (size_t)H_ * K2_;
        int lw = (int)(j / per);
        size_t rem = j % per;
        int n = (int)(rem / K2_);
        int k = (int)(rem % K2_);
        float v = (k < H_) ? Wihr[(size_t)lw * HH + (size_t)n * H_ + k]
                           : Whh[(size_t)(lw + 1) * HH + (size_t)n * H_ + (k - H_)];
        __half a = __float2half(v);
        wch[j] = a;
        wcl[j] = __float2half((v - __half2float(a)) * RSCALE);
    }
}

// ---------------------------------------------------------------------------
// Persistent wavefront kernel, BALANCED 148-CTA static schedule.
// Tiles: layer0: 32 tiles (K=2048=32 chunks); layers1-3: 96 tiles (K=4096=64).
// Jobs (chunk units of K=64):
//   CTA 0..95   : OWN  tile q=c (layer 1+c/32): k-chunks [0,48)        = 48
//   CTA 96..127 : L0   tile idx=c-96 full (32) + HELP q3 of q=idx (16) = 48
//   CTA 128..139: HELP 3 q3 jobs (q=32+3h..)                           = 48
//   CTA 140..147: HELP 1 eighth (q=92+(e>>1), 8) + 3 q3 (q=68+3(h-12)) = 56
// Helpers write merged fp32 partials (acc + corr/1024) to g_PART[q] (slot 1
// -> g_PART2) then flag; owners spin on the monotonic flag, add, epilogue.
// All 148 CTAs co-resident (1/SM) -> grid barrier + owner spins are safe.
// ---------------------------------------------------------------------------
__device__ __forceinline__ void grid_barrier(unsigned target) {
    __threadfence();
    __syncthreads();
    if (threadIdx.x == 0) {
        atomicAdd(&g_bar, 1u);
        while (*((volatile unsigned*)&g_bar) < target) { }
        __threadfence();
    }
    __syncthreads();
}

__global__ __launch_bounds__(WTHREADS, 1)
void wave_kernel(const float* __restrict__ XP0, const float* __restrict__ b_ihr)
{
    extern __shared__ __half sm[];
    __shared__ __align__(8) unsigned long long s_mbar[2 * NSTAGE];

    const int tid  = threadIdx.x;
    const int warp = tid >> 5, lane = tid & 31;
    const int c    = blockIdx.x;

    const unsigned mb = sptr(&s_mbar[0]);
    if (tid == 0) {
        #pragma unroll
        for (int s = 0; s < NSTAGE; s++) {
            mbar_init(mb + s * 8, WTHREADS);
            mbar_init(mb + (NSTAGE + s) * 8, WTHREADS);
        }
    }
    __syncthreads();

    // ---- static job table (uniform per CTA) ----
    int jl[4], jbm[4], jbn[4], jk0[4], jkn[4], jmode[4], jq[4], jslot[4];
    #pragma unroll
    for (int j = 0; j < 4; j++) { jl[j] = 0; jbm[j] = 0; jbn[j] = 0; jk0[j] = 0;
                                  jkn[j] = 0; jmode[j] = MODE_NONE; jq[j] = 0; jslot[j] = 0; }
    if (c < 96) {
        int l = 1 + c / 32, r = c % 32;
        jl[0] = l; jbm[0] = (r & 1) * 128; jbn[0] = (r >> 1) * 128;
        jk0[0] = 0; jkn[0] = 48; jmode[0] = MODE_OWN; jq[0] = c;
    } else if (c < 128) {
        int idx = c - 96;
        jl[0] = 0; jbm[0] = (idx & 1) * 128; jbn[0] = (idx >> 1) * 128;
        jk0[0] = 0; jkn[0] = 32; jmode[0] = MODE_L0;
        int q = idx, l = 1 + q / 32, r = q % 32;
        jl[1] = l; jbm[1] = (r & 1) * 128; jbn[1] = (r >> 1) * 128;
        jk0[1] = 48; jkn[1] = 16; jmode[1] = MODE_HELP; jq[1] = q; jslot[1] = 0;
    } else {
        int h = c - 128, n = 0;
        if (h >= 12) {                              // eighth job FIRST (early partial)
            int e = h - 12, q = 92 + (e >> 1), l = 1 + q / 32, r = q % 32;
            jl[n] = l; jbm[n] = (r & 1) * 128; jbn[n] = (r >> 1) * 128;
            jk0[n] = 48 + (e & 1) * 8; jkn[n] = 8; jmode[n] = MODE_HELP;
            jq[n] = q; jslot[n] = e & 1; n++;
        }
        int qb = (h < 12) ? (32 + h * 3) : (68 + (h - 12) * 3);
        for (int i = 0; i < 3; i++) {
            int q = qb + i, l = 1 + q / 32, r = q % 32;
            jl[n] = l; jbm[n] = (r & 1) * 128; jbn[n] = (r >> 1) * 128;
            jk0[n] = 48; jkn[n] = 16; jmode[n] = MODE_HELP; jq[n] = q; jslot[n] = 0; n++;
        }
    }

    const int wm = (warp & 3) * 32;
    const int wn = (warp >> 2) * 32;
    const int a_row = lane & 15;
    const int a_k   = (lane >> 4) * 8;
    const int b_row = (lane & 7) + ((lane >> 4) << 3);
    const int b_k   = ((lane >> 3) & 1) * 8;
    const int ldrow = tid >> 3;
    const int ldc   = (tid & 7) * 8;

    unsigned pf = 0, pe = 0;
    unsigned gf = 0, gc = 0;
    unsigned expQ = 0;                    // owner's expected flag count (monotonic)

    float acch[2][4][4];
    unsigned accc[2][4][2];

    for (int s = 0; s < T_ + L_ - 1; ++s) {
        // active chunk counts per job
        int an[4], tjv[4], tot = 0;
        #pragma unroll
        for (int j = 0; j < 4; j++) {
            an[j] = 0; tjv[j] = -1;
            if (jkn[j] > 0) {
                int tj = s - jl[j];
                tjv[j] = tj;
                if (tj >= 0 && tj < T_) {
                    int ke = (jl[j] == 0) ? (tj == 0 ? 0 : 32) : (tj == 0 ? 32 : 64);
                    int hi = jk0[j] + jkn[j]; if (hi > ke) hi = ke;
                    if (hi > jk0[j]) an[j] = hi - jk0[j];
                }
            }
            tot += an[j];
        }

        // fill flat index fi -> (job, chunk); includes empty-wait + cp-arrive
        auto doFill = [&](int fi) {
            int j = 0, base = 0;
            while (fi >= base + an[j]) { base += an[j]; j++; }
            const int kc = jk0[j] + (fi - base);          // chunk index in K
            const int l  = jl[j];
            const int st = (int)(gf % NSTAGE);
            if (gf >= NSTAGE) {
                mbar_wait(mb + (NSTAGE + st) * 8, (pe >> st) & 1u);
                pe ^= 1u << st;
            }
            __half* basep = sm + st * STAGE_E;
            const int k0e = kc * CHUNK;
            // A planes
            {
                const int tj = tjv[j];
                const __half *Ah_g, *Al_g; int ak;
                if (l == 0) {
                    size_t off = (size_t)((tj - 1) & 1) * BH_;
                    Ah_g = g_Hh + off; Al_g = g_Hl + off; ak = k0e;
                } else if (k0e < H_) {
                    size_t off = (size_t)((l - 1) * 2 + (tj & 1)) * BH_;
                    Ah_g = g_Hh + off; Al_g = g_Hl + off; ak = k0e;
                } else {
                    size_t off = (size_t)(l * 2 + ((tj - 1) & 1)) * BH_;
                    Ah_g = g_Hh + off; Al_g = g_Hl + off; ak = k0e - H_;
                }
                #pragma unroll
                for (int i = 0; i < 2; i++) {
                    int row = ldrow + i * 64;
                    size_t ga = (size_t)(jbm[j] + row) * H_ + ak + ldc;
                    int so = row * PITCH + ldc;
                    cp16(basep + so,          Ah_g + ga);
                    cp16(basep + TILE_E + so, Al_g + ga);
                }
            }
            // B planes
            {
                const int Kl = (l == 0) ? H_ : K2_;
                const __half* WBh = (l == 0) ? (g_W0h + (size_t)jbn[j] * H_)
                    : (g_Wch + ((size_t)(l - 1) * H_ + jbn[j]) * K2_);
                const __half* WBl = (l == 0) ? (g_W0l + (size_t)jbn[j] * H_)
                    : (g_Wcl + ((size_t)(l - 1) * H_ + jbn[j]) * K2_);
                #pragma unroll
                for (int i = 0; i < 2; i++) {
                    int row = ldrow + i * 64;
                    size_t gb = (size_t)row * Kl + k0e + ldc;
                    int so = row * PITCH + ldc;
                    cp16(basep + 2 * TILE_E + so, WBh + gb);
                    cp16(basep + 3 * TILE_E + so, WBl + gb);
                }
            }
            cp_arrive_noinc(mb + st * 8);
            gf++;
        };

        auto computeChunk = [&](int stg) {
            const __half* base = sm + stg * STAGE_E;
            #pragma unroll
            for (int kk = 0; kk < 4; kk++) {
                unsigned ah[2][4], al[2][4], bh[4][2], bl[4][2];
                #pragma unroll
                for (int i = 0; i < 2; i++) {
                    const __half* pa = base + (wm + i * 16 + a_row) * PITCH + kk * 16 + a_k;
                    ldsm4(ah[i][0], ah[i][1], ah[i][2], ah[i][3], pa);
                    ldsm4(al[i][0], al[i][1], al[i][2], al[i][3], pa + TILE_E);
                }
                #pragma unroll
                for (int jp = 0; jp < 2; jp++) {
                    const __half* pb =
                        base + 2 * TILE_E + (wn + jp * 16 + b_row) * PITCH + kk * 16 + b_k;
                    unsigned r0, r1, r2, r3;
                    ldsm4(r0, r1, r2, r3, pb);
                    bh[jp * 2][0] = r0; bh[jp * 2][1] = r1;
                    bh[jp * 2 + 1][0] = r2; bh[jp * 2 + 1][1] = r3;
                    ldsm4(r0, r1, r2, r3, pb + TILE_E);
                    bl[jp * 2][0] = r0; bl[jp * 2][1] = r1;
                    bl[jp * 2 + 1][0] = r2; bl[jp * 2 + 1][1] = r3;
                }
                #pragma unroll
                for (int i = 0; i < 2; i++)
                    #pragma unroll
                    for (int j2 = 0; j2 < 4; j2++) {
                        mma_f32acc(acch[i][j2], ah[i], bh[j2]);
                        mma_f16acc(accc[i][j2], ah[i], bl[j2]);
                        mma_f16acc(accc[i][j2], al[i], bh[j2]);
                    }
            }
        };

        if (tot > 0) { doFill(0); if (tot > 1) doFill(1); }

        int done = 0;
        for (int j = 0; j < 4; j++) {
            if (jkn[j] == 0) continue;
            const int tj = tjv[j];
            if (tj < 0 || tj >= T_) continue;

            // zero accumulators for this job
            #pragma unroll
            for (int i = 0; i < 2; i++)
                #pragma unroll
                for (int j2 = 0; j2 < 4; j2++) {
                    #pragma unroll
                    for (int q2 = 0; q2 < 4; q2++) acch[i][j2][q2] = 0.f;
                    accc[i][j2][0] = 0u; accc[i][j2][1] = 0u;
                }

            for (int cc = 0; cc < an[j]; ++cc) {
                const int sc = (int)(gc % NSTAGE);
                mbar_wait(mb + sc * 8, (pf >> sc) & 1u);
                pf ^= 1u << sc;
                const int nf = done + cc + 2;
                if (nf < tot) doFill(nf);
                computeChunk(sc);
                mbar_arrive(mb + (NSTAGE + sc) * 8);
                gc++;
            }
            done += an[j];

            if (jmode[j] == MODE_HELP) {
                if (an[j] > 0) {
                    float* P = (jslot[j] == 0) ? g_PART[jq[j]] : g_PART2[jq[j] - 92];
                    #pragma unroll
                    for (int i = 0; i < 2; i++) {
                        const int m0 = wm + i * 16 + (lane >> 2);
                        #pragma unroll
                        for (int j2 = 0; j2 < 4; j2++) {
                            const int n0 = wn + j2 * 8 + (lane & 3) * 2;
                            __half2 c01 = *(__half2*)&accc[i][j2][0];
                            __half2 c23 = *(__half2*)&accc[i][j2][1];
                            float2 v0, v1;
                            v0.x = acch[i][j2][0] + __half2float(c01.x) * INV_RS;
                            v0.y = acch[i][j2][1] + __half2float(c01.y) * INV_RS;
                            v1.x = acch[i][j2][2] + __half2float(c23.x) * INV_RS;
                            v1.y = acch[i][j2][3] + __half2float(c23.y) * INV_RS;
                            *(float2*)(P + (size_t)m0 * 128 + n0) = v0;
                            *(float2*)(P + (size_t)(m0 + 8) * 128 + n0) = v1;
                        }
                    }
                    __threadfence();
                    __syncthreads();
                    if (tid == 0) atomicAdd(&g_flag[jq[j]], 1u);
                }
            } else {
                // epilogue (MODE_L0 immediate; MODE_OWN after merging partials)
                const float* P1 = nullptr; const float* P2 = nullptr;
                if (jmode[j] == MODE_OWN) {
                    const int contrib = (tj >= 1) ? ((jq[j] >= 92) ? 2 : 1) : 0;
                    expQ += (unsigned)contrib;
                    if (tid == 0) {
                        while (*((volatile unsigned*)&g_flag[jq[j]]) < expQ) { }
                        __threadfence();
                    }
                    __syncthreads();
                    if (tj >= 1) {
                        P1 = g_PART[jq[j]];
                        if (jq[j] >= 92) P2 = g_PART2[jq[j] - 92];
                    }
                }
                const bool hasMMA = (an[j] > 0);
                const int l = jl[j];
                const size_t hoff = (size_t)(l * 2 + (tj & 1)) * BH_;
                #pragma unroll
                for (int i = 0; i < 2; i++) {
                    const int ml = wm + i * 16 + (lane >> 2);
                    const int m0 = jbm[j] + ml;
                    #pragma unroll
                    for (int j2 = 0; j2 < 4; j2++) {
                        const int nl = wn + j2 * 8 + (lane & 3) * 2;
                        const int n0 = jbn[j] + nl;
                        float a0, a1, a2, a3;
                        if (l == 0) {
                            const float* xp = XP0 + (size_t)tj * BH_;
                            float2 u = *(const float2*)(xp + (size_t)m0 * H_ + n0);
                            float2 w = *(const float2*)(xp + (size_t)(m0 + 8) * H_ + n0);
                            a0 = u.x; a1 = u.y; a2 = w.x; a3 = w.y;
                        } else {
                            float2 u = *(const float2*)(b_ihr + (size_t)(l - 1) * H_ + n0);
                            a0 = u.x; a1 = u.y; a2 = u.x; a3 = u.y;
                        }
                        float v0 = a0, v1 = a1, v2 = a2, v3 = a3;
                        if (hasMMA) {
                            __half2 c01 = *(__half2*)&accc[i][j2][0];
                            __half2 c23 = *(__half2*)&accc[i][j2][1];
                            v0 += acch[i][j2][0] + __half2float(c01.x) * INV_RS;
                            v1 += acch[i][j2][1] + __half2float(c01.y) * INV_RS;
                            v2 += acch[i][j2][2] + __half2float(c23.x) * INV_RS;
                            v3 += acch[i][j2][3] + __half2float(c23.y) * INV_RS;
                        }
                        if (P1) {
                            float2 p0 = *(const float2*)(P1 + (size_t)ml * 128 + nl);
                            float2 p1 = *(const float2*)(P1 + (size_t)(ml + 8) * 128 + nl);
                            v0 += p0.x; v1 += p0.y; v2 += p1.x; v3 += p1.y;
                        }
                        if (P2) {
                            float2 p0 = *(const float2*)(P2 + (size_t)ml * 128 + nl);
                            float2 p1 = *(const float2*)(P2 + (size_t)(ml + 8) * 128 + nl);
                            v0 += p0.x; v1 += p0.y; v2 += p1.x; v3 += p1.y;
                        }
                        v0 = tanhf(v0); v1 = tanhf(v1); v2 = tanhf(v2); v3 = tanhf(v3);

                        __half h0 = __float2half(v0), h1 = __float2half(v1);
                        __half h2 = __float2half(v2), h3 = __float2half(v3);
                        __half2 ph, pl;
                        ph.x = h0; ph.y = h1;
                        pl.x = __float2half((v0 - __half2float(h0)) * RSCALE);
                        pl.y = __float2half((v1 - __half2float(h1)) * RSCALE);
                        *(__half2*)(g_Hh + hoff + (size_t)m0 * H_ + n0) = ph;
                        *(__half2*)(g_Hl + hoff + (size_t)m0 * H_ + n0) = pl;
                        ph.x = h2; ph.y = h3;
                        pl.x = __float2half((v2 - __half2float(h2)) * RSCALE);
                        pl.y = __float2half((v3 - __half2float(h3)) * RSCALE);
                        *(__half2*)(g_Hh + hoff + (size_t)(m0 + 8) * H_ + n0) = ph;
                        *(__half2*)(g_Hl + hoff + (size_t)(m0 + 8) * H_ + n0) = pl;
                    }
                }
            }
        }

        grid_barrier((unsigned)(s + 1) * NCTA);
    }
}

// ---------------------------------------------------------------------------
// Final FC: out[b] = (hi + lo/1024)[b,:] @ W_fc^T + b_fc
// ---------------------------------------------------------------------------
__global__ void fc_kernel(const __half* __restrict__ hh,
                          const __half* __restrict__ hl,
                          const float* __restrict__ w, const float* __restrict__ bfc,
                          float* __restrict__ out) {
    __shared__ float red[256];
    const size_t base = (size_t)blockIdx.x * H_;
    float s = 0.f;
    for (int j = threadIdx.x; j < H_; j += 256) {
        float hv = __half2float(hh[base + j]) + __half2float(hl[base + j]) * INV_RS;
        s = fmaf(hv, w[j], s);
    }
    red[threadIdx.x] = s;
    __syncthreads();
    for (int off = 128; off; off >>= 1) {
        if (threadIdx.x < off) red[threadIdx.x] += red[threadIdx.x + off];
        __syncthreads();
    }
    if (threadIdx.x == 0) out[blockIdx.x] = red[0] + bfc[0];
}

// ---------------------------------------------------------------------------
extern "C" void kernel_launch(void* const* d_in, const int* in_sizes, int n_in,
                              void* d_out, int out_size)
{
    const float* x      = (const float*)d_in[0];
    const float* W_ih0  = (const float*)d_in[1];
    const float* b_ih0  = (const float*)d_in[2];
    const float* W_ihr  = (const float*)d_in[3];
    const float* b_ihr  = (const float*)d_in[4];
    const float* W_hh   = (const float*)d_in[5];
    const float* W_fc   = (const float*)d_in[6];
    const float* b_fc   = (const float*)d_in[7];
    float* out = (float*)d_out;

    float *XT, *XP;
    __half *W0h, *W0l, *Wch, *Wcl, *Hh, *Hl;
    unsigned *bar, *flag;
    cudaGetSymbolAddress((void**)&XT,   g_XT);
    cudaGetSymbolAddress((void**)&XP,   g_XP);
    cudaGetSymbolAddress((void**)&W0h,  g_W0h);
    cudaGetSymbolAddress((void**)&W0l,  g_W0l);
    cudaGetSymbolAddress((void**)&Wch,  g_Wch);
    cudaGetSymbolAddress((void**)&Wcl,  g_Wcl);
    cudaGetSymbolAddress((void**)&Hh,   g_Hh);
    cudaGetSymbolAddress((void**)&Hl,   g_Hl);
    cudaGetSymbolAddress((void**)&bar,  g_bar);
    cudaGetSymbolAddress((void**)&flag, g_flag);

    static int smem_set = 0;
    if (!smem_set) {
        cudaFuncSetAttribute(wave_kernel, cudaFuncAttributeMaxDynamicSharedMemorySize,
                             DYN_SMEM);
        smem_set = 1;
    }

    cudaMemsetAsync(bar, 0, sizeof(unsigned));
    cudaMemsetAsync(flag, 0, 96 * sizeof(unsigned));

    transpose_x<<<(T_ * B_ * (I_ / 4)) / 256, 256>>>(x, XT);

    gemm_nt<128, 64, 16, 8, 4><<<dim3(H_ / 64, (T_ * B_) / 128), 256>>>(
        XT, W_ih0, b_ih0, XP, T_ * B_, H_, I_);

    {
        const size_t total = (size_t)H_ * H_ + (size_t)3 * H_ * K2_;
        prep_weights<<<(unsigned)(total / 256), 256>>>(W_hh, W_ihr, W0h, W0l, Wch, Wcl);
    }

    wave_kernel<<<NCTA, WTHREADS, DYN_SMEM>>>(XP, b_ihr);

    fc_kernel<<<B_, 256>>>(Hh + (size_t)(3 * 2 + 1) * BH_,
                           Hl + (size_t)(3 * 2 + 1) * BH_, W_fc, b_fc, out);
}

// round 17
// speedup vs baseline: 1.0969x; 1.0969x over previous
#include <cuda_runtime.h>
#include <cuda_fp16.h>
#include <math.h>
#include <stdint.h>

#define B_  256
#define T_  256
#define I_  64
#define H_  2048
#define L_  4
#define BH_ (B_ * H_)
#define K2_ 4096

// ---- wave kernel tiling: CTA tile 128x128, K chunk 64 (fp16), 3 stages ----
#define CHUNK    64
#define PITCH    72                      // fp16 elems per smem row (144B)
#define TILE_E   (128 * PITCH)           // one operand plane (elems)
#define STAGE_E  (4 * TILE_E)            // Ah, Al, Bh, Bl planes
#define NSTAGE   3
#define DYN_SMEM (NSTAGE * STAGE_E * 2)  // 221184 bytes
#define WTHREADS 512
#define RSCALE   1024.f                  // residual digit scale (2^10)
#define INV_RS   (1.f / 1024.f)

// ---- device scratch (allocation-free contract) ----
__device__ float g_XT[(size_t)T_ * B_ * I_];
__device__ float g_XP[(size_t)T_ * B_ * H_];                 // layer-0 input projection
__device__ __half g_W0h[(size_t)H_ * H_];
__device__ __half g_W0l[(size_t)H_ * H_];
__device__ __half g_Wch[(size_t)3 * H_ * K2_];               // [Wih ; Whh] concat, layers 1..3
__device__ __half g_Wcl[(size_t)3 * H_ * K2_];
__device__ __half g_Hh[(size_t)L_ * 2 * BH_];                // h ping-pong, hi digit
__device__ __half g_Hl[(size_t)L_ * 2 * BH_];                // lo digit (x1024)
__device__ unsigned g_bar;

// ---------------------------------------------------------------------------
// helpers
// ---------------------------------------------------------------------------
__device__ __forceinline__ unsigned sptr(const void* p) {
    return (unsigned)__cvta_generic_to_shared(p);
}
__device__ __forceinline__ void cp16(__half* s, const __half* g) {
    asm volatile("cp.async.cg.shared.global [%0], [%1], 16;" :: "r"(sptr(s)), "l"(g));
}
__device__ __forceinline__ void ldsm4(unsigned& r0, unsigned& r1, unsigned& r2,
                                      unsigned& r3, const __half* p) {
    asm volatile("ldmatrix.sync.aligned.m8n8.x4.shared.b16 {%0,%1,%2,%3}, [%4];"
                 : "=r"(r0), "=r"(r1), "=r"(r2), "=r"(r3) : "r"(sptr(p)));
}
// fp16 inputs, fp32 accumulate (hi*hi pass)
__device__ __forceinline__ void mma_f32acc(float* d, const unsigned* a, const unsigned* b) {
    asm volatile("mma.sync.aligned.m16n8k16.row.col.f32.f16.f16.f32 "
                 "{%0,%1,%2,%3}, {%4,%5,%6,%7}, {%8,%9}, {%0,%1,%2,%3};"
                 : "+f"(d[0]), "+f"(d[1]), "+f"(d[2]), "+f"(d[3])
                 : "r"(a[0]), "r"(a[1]), "r"(a[2]), "r"(a[3]), "r"(b[0]), "r"(b[1]));
}
// fp16 inputs, fp16 accumulate (correction passes)
__device__ __forceinline__ void mma_f16acc(unsigned* d, const unsigned* a, const unsigned* b) {
    asm volatile("mma.sync.aligned.m16n8k16.row.col.f16.f16.f16.f16 "
                 "{%0,%1}, {%2,%3,%4,%5}, {%6,%7}, {%0,%1};"
                 : "+r"(d[0]), "+r"(d[1])
                 : "r"(a[0]), "r"(a[1]), "r"(a[2]), "r"(a[3]), "r"(b[0]), "r"(b[1]));
}
__device__ __forceinline__ void mbar_init(unsigned mbar, unsigned cnt) {
    asm volatile("mbarrier.init.shared.b64 [%0], %1;" :: "r"(mbar), "r"(cnt) : "memory");
}
__device__ __forceinline__ void mbar_arrive(unsigned mbar) {
    asm volatile("mbarrier.arrive.shared.b64 _, [%0];" :: "r"(mbar) : "memory");
}
__device__ __forceinline__ void cp_arrive_noinc(unsigned mbar) {
    asm volatile("cp.async.mbarrier.arrive.noinc.shared.b64 [%0];" :: "r"(mbar) : "memory");
}
__device__ __forceinline__ void mbar_wait(unsigned mbar, unsigned phase) {
    asm volatile(
        "{\n\t.reg .pred P1;\n\t"
        "WAIT_LOOP_%=:\n\t"
        "mbarrier.try_wait.parity.shared.b64 P1, [%0], %1;\n\t"
        "@P1 bra.uni WAIT_DONE_%=;\n\t"
        "bra.uni WAIT_LOOP_%=;\n\t"
        "WAIT_DONE_%=:\n\t}"
        :: "r"(mbar), "r"(phase) : "memory");
}

// ---------------------------------------------------------------------------
// x[B,T,I] -> XT[T,B,I]
// ---------------------------------------------------------------------------
__global__ void transpose_x(const float* __restrict__ x, float* __restrict__ xt) {
    int idx = blockIdx.x * blockDim.x + threadIdx.x;
    int i4 = idx & 15;
    int b  = (idx >> 4) & (B_ - 1);
    int t  = idx >> 12;
    float4 v = *(const float4*)(x + ((size_t)b * T_ + t) * I_ + i4 * 4);
    *(float4*)(xt + ((size_t)t * B_ + b) * I_ + i4 * 4) = v;
}

// ---------------------------------------------------------------------------
// fp32 NT GEMM (layer-0 input projection, K=64): C = A@W^T + bias
// ---------------------------------------------------------------------------
template<int BM, int BN, int BK, int TM, int TN>
__global__ __launch_bounds__((BM / TM) * (BN / TN))
void gemm_nt(const float* __restrict__ A, const float* __restrict__ W,
             const float* __restrict__ bias, float* __restrict__ C,
             int M, int N, int K)
{
    constexpr int NT  = (BM / TM) * (BN / TN);
    constexpr int KV  = BK / 4;
    constexpr int AV  = (BM * BK) / (NT * 4);
    constexpr int BV  = (BN * BK) / (NT * 4);
    constexpr int ARS = NT / KV;

    __shared__ __align__(16) float As[BK][BM + 4];
    __shared__ __align__(16) float Bs[BK][BN + 4];

    const int tid = threadIdx.x;
    const int bm  = blockIdx.y * BM;
    const int bn  = blockIdx.x * BN;
    const int lr = tid / KV;
    const int lc = (tid % KV) * 4;
    const float* Ag = A + (size_t)(bm + lr) * K + lc;
    const float* Wg = W + (size_t)(bn + lr) * K + lc;
    const int tx = tid % (BN / TN);
    const int ty = tid / (BN / TN);

    float acc[TM][TN];
    #pragma unroll
    for (int i = 0; i < TM; i++)
        #pragma unroll
        for (int j = 0; j < TN; j++) acc[i][j] = 0.f;

    float4 ra[AV], rb[BV];
    #pragma unroll
    for (int v = 0; v < AV; v++) ra[v] = *(const float4*)(Ag + (size_t)v * ARS * K);
    #pragma unroll
    for (int v = 0; v < BV; v++) rb[v] = *(const float4*)(Wg + (size_t)v * ARS * K);

    for (int k0 = 0; k0 < K; k0 += BK) {
        __syncthreads();
        #pragma unroll
        for (int v = 0; v < AV; v++) {
            As[lc + 0][lr + v * ARS] = ra[v].x; As[lc + 1][lr + v * ARS] = ra[v].y;
            As[lc + 2][lr + v * ARS] = ra[v].z; As[lc + 3][lr + v * ARS] = ra[v].w;
        }
        #pragma unroll
        for (int v = 0; v < BV; v++) {
            Bs[lc + 0][lr + v * ARS] = rb[v].x; Bs[lc + 1][lr + v * ARS] = rb[v].y;
            Bs[lc + 2][lr + v * ARS] = rb[v].z; Bs[lc + 3][lr + v * ARS] = rb[v].w;
        }
        __syncthreads();
        if (k0 + BK < K) {
            #pragma unroll
            for (int v = 0; v < AV; v++) ra[v] = *(const float4*)(Ag + (size_t)v * ARS * K + k0 + BK);
            #pragma unroll
            for (int v = 0; v < BV; v++) rb[v] = *(const float4*)(Wg + (size_t)v * ARS * K + k0 + BK);
        }
        #pragma unroll
        for (int kk = 0; kk < BK; ++kk) {
            float a[TM], b[TN];
            #pragma unroll
            for (int i = 0; i < TM; i += 4) *(float4*)&a[i] = *(const float4*)&As[kk][ty * TM + i];
            #pragma unroll
            for (int j = 0; j < TN; j += 4) *(float4*)&b[j] = *(const float4*)&Bs[kk][tx * TN + j];
            #pragma unroll
            for (int i = 0; i < TM; i++)
                #pragma unroll
                for (int j = 0; j < TN; j++) acc[i][j] = fmaf(a[i], b[j], acc[i][j]);
        }
    }
    const int n0 = bn + tx * TN;
    float4 bia = *(const float4*)(bias + n0);
    #pragma unroll
    for (int i = 0; i < TM; i++) {
        const size_t row = (size_t)(bm + ty * TM + i) * N + n0;
        float4 v;
        v.x = acc[i][0] + bia.x; v.y = acc[i][1] + bia.y;
        v.z = acc[i][2] + bia.z; v.w = acc[i][3] + bia.w;
        *(float4*)(C + row) = v;
    }
}

// ---------------------------------------------------------------------------
// weight precompute (merged): fp32 -> fp16 hi + scaled fp16 lo
// ---------------------------------------------------------------------------
__global__ void prep_weights(const float* __restrict__ Whh, const float* __restrict__ Wihr,
                             __half* __restrict__ w0h, __half* __restrict__ w0l,
                             __half* __restrict__ wch, __half* __restrict__ wcl)
{
    const size_t HH = (size_t)H_ * H_;
    size_t i = (size_t)blockIdx.x * blockDim.x + threadIdx.x;
    if (i < HH) {
        float v = Whh[i];
        __half a = __float2half(v);
        w0h[i] = a;
        w0l[i] = __float2half((v - __half2float(a)) * RSCALE);
    } else {
        size_t j = i - HH;
        const size_t per = (size_t)H_ * K2_;
        int lw = (int)(j / per);
        size_t rem = j % per;
        int n = (int)(rem / K2_);
        int k = (int)(rem % K2_);
        float v = (k < H_) ? Wihr[(size_t)lw * HH + (size_t)n * H_ + k]
                           : Whh[(size_t)(lw + 1) * HH + (size_t)n * H_ + (k - H_)];
        __half a = __float2half(v);
        wch[j] = a;
        wcl[j] = __float2half((v - __half2float(a)) * RSCALE);
    }
}

// ---------------------------------------------------------------------------
// Persistent wavefront kernel: 128 CTAs = 4 layers x (2 m x 16 n tiles),
// CTA tile 128x128, 512 threads (16 warps, 32x32 warp tiles), fp16 2-digit
// split (hi*hi fp32-accum, corrections fp16-accum), 3-stage mbarrier pipeline.
// Cross-barrier B prefetch, hoisted ABOVE the epilogue so the B loads for the
// next step's first two chunks overlap the epilogue's tanh/stores in addition
// to the grid-barrier wait.
// ---------------------------------------------------------------------------
__device__ __forceinline__ void grid_barrier(unsigned target) {
    __threadfence();
    __syncthreads();
    if (threadIdx.x == 0) {
        atomicAdd(&g_bar, 1u);
        while (*((volatile unsigned*)&g_bar) < target) { }
        __threadfence();
    }
    __syncthreads();
}

__global__ __launch_bounds__(WTHREADS, 1)
void wave_kernel(const float* __restrict__ XP0, const float* __restrict__ b_ihr)
{
    extern __shared__ __half sm[];
    __shared__ __align__(8) unsigned long long s_mbar[2 * NSTAGE];  // full[3], empty[3]

    const int tid  = threadIdx.x;
    const int warp = tid >> 5, lane = tid & 31;
    const int l  = blockIdx.x >> 5;
    const int rr = blockIdx.x & 31;
    const int bm = (rr & 1) * 128;
    const int bn = (rr >> 1) * 128;

    const unsigned mb = sptr(&s_mbar[0]);
    if (tid == 0) {
        #pragma unroll
        for (int s = 0; s < NSTAGE; s++) {
            mbar_init(mb + s * 8, WTHREADS);                 // full[s]
            mbar_init(mb + (NSTAGE + s) * 8, WTHREADS);      // empty[s]
        }
    }
    __syncthreads();

    const int Kl = (l == 0) ? H_ : K2_;
    const __half* WBh = (l == 0) ? (g_W0h + (size_t)bn * H_)
                                 : (g_Wch + (size_t)(l - 1) * H_ * K2_ + (size_t)bn * K2_);
    const __half* WBl = (l == 0) ? (g_W0l + (size_t)bn * H_)
                                 : (g_Wcl + (size_t)(l - 1) * H_ * K2_ + (size_t)bn * K2_);

    const int wm = (warp & 3) * 32;      // 4 m sub-tiles of 32
    const int wn = (warp >> 2) * 32;     // 4 n sub-tiles of 32
    const int a_row = lane & 15;
    const int a_k   = (lane >> 4) * 8;
    const int b_row = (lane & 7) + ((lane >> 4) << 3);
    const int b_k   = ((lane >> 3) & 1) * 8;
    const int ldrow = tid >> 3;          // 0..63
    const int ldc   = (tid & 7) * 8;     // elems

    // pipeline state (uniform across CTA; persists across wavefront steps)
    unsigned pf = 0, pe = 0;             // parity bits, one per stage
    unsigned gf = 0, gc = 0;             // monotonic fill / compute counters
    bool preB = false;                   // B of chunks 0,1 already issued pre-barrier

    // B-plane loader into a resolved stage (step-invariant addresses)
    auto loadB = [&](int st, int k0) {
        __half* base = sm + st * STAGE_E;
        #pragma unroll
        for (int i = 0; i < 2; i++) {
            int row = ldrow + i * 64;
            size_t gb = (size_t)row * Kl + k0 + ldc;
            int so = row * PITCH + ldc;
            cp16(base + 2 * TILE_E + so, WBh + gb);
            cp16(base + 3 * TILE_E + so, WBl + gb);
        }
    };

    // cross-barrier B prefetch for step s+1 (chunks 0,1); consumes empty tokens
    auto doPreB = [&](int s) {
        const int t2 = s + 1 - l;
        const bool act2 = (t2 >= 0 && t2 < T_);
        const int kEnd2 = act2 ? ((l == 0) ? (t2 == 0 ? 0 : H_) : (t2 == 0 ? H_ : K2_)) : 0;
        preB = false;
        if (kEnd2 > 0) {
            #pragma unroll
            for (int c = 0; c < 2; ++c) {
                const int st = (int)((gf + c) % NSTAGE);
                if (gf + c >= NSTAGE) {            // consume empty token now
                    mbar_wait(mb + (NSTAGE + st) * 8, (pe >> st) & 1u);
                    pe ^= 1u << st;
                }
                loadB(st, c * CHUNK);              // B is step-invariant: safe pre-barrier
            }
            preB = true;
        }
    };

    for (int s = 0; s < T_ + L_ - 1; ++s) {
        const int t = s - l;
        const bool act = (t >= 0 && t < T_);
        const int kEnd = act ? ((l == 0) ? (t == 0 ? 0 : H_) : (t == 0 ? H_ : K2_)) : 0;

        if (act) {
            float acch[2][4][4];         // hi*hi, fp32 accum
            unsigned accc[2][4][2];      // corrections, fp16 accum (half2 x2)
            #pragma unroll
            for (int i = 0; i < 2; i++)
                #pragma unroll
                for (int j = 0; j < 4; j++) {
                    #pragma unroll
                    for (int q = 0; q < 4; q++) acch[i][j][q] = 0.f;
                    accc[i][j][0] = 0u; accc[i][j][1] = 0u;
                }

            auto loadA = [&](int st, int k0) {
                __half* base = sm + st * STAGE_E;
                const __half *Ah_g, *Al_g;
                int ak;
                if (l == 0) {                       // A = h^0_{t-1}
                    size_t off = (size_t)((t - 1) & 1) * BH_;
                    Ah_g = g_Hh + off; Al_g = g_Hl + off; ak = k0;
                } else if (k0 < H_) {               // A = h^{l-1}_t
                    size_t off = (size_t)((l - 1) * 2 + (t & 1)) * BH_;
                    Ah_g = g_Hh + off; Al_g = g_Hl + off; ak = k0;
                } else {                            // A = h^l_{t-1}
                    size_t off = (size_t)(l * 2 + ((t - 1) & 1)) * BH_;
                    Ah_g = g_Hh + off; Al_g = g_Hl + off; ak = k0 - H_;
                }
                #pragma unroll
                for (int i = 0; i < 2; i++) {
                    int row = ldrow + i * 64;
                    size_t ga = (size_t)(bm + row) * H_ + ak + ldc;
                    int so = row * PITCH + ldc;
                    cp16(base + so,          Ah_g + ga);
                    cp16(base + TILE_E + so, Al_g + ga);
                }
            };

            // full fill (A+B, with empty-wait) for chunks >= 2
            auto fill = [&](int k0) {
                const int st = (int)(gf % NSTAGE);
                if (gf >= NSTAGE) {
                    mbar_wait(mb + (NSTAGE + st) * 8, (pe >> st) & 1u);
                    pe ^= 1u << st;
                }
                loadA(st, k0);
                loadB(st, k0);
                cp_arrive_noinc(mb + st * 8);
                gf++;
            };

            auto compute = [&](int stg) {
                const __half* base = sm + stg * STAGE_E;
                #pragma unroll
                for (int kk = 0; kk < 4; kk++) {
                    unsigned ah[2][4], al[2][4], bh[4][2], bl[4][2];
                    #pragma unroll
                    for (int i = 0; i < 2; i++) {
                        const __half* pa =
                            base + (wm + i * 16 + a_row) * PITCH + kk * 16 + a_k;
                        ldsm4(ah[i][0], ah[i][1], ah[i][2], ah[i][3], pa);
                        ldsm4(al[i][0], al[i][1], al[i][2], al[i][3], pa + TILE_E);
                    }
                    #pragma unroll
                    for (int jp = 0; jp < 2; jp++) {
                        const __half* pb =
                            base + 2 * TILE_E + (wn + jp * 16 + b_row) * PITCH + kk * 16 + b_k;
                        unsigned r0, r1, r2, r3;
                        ldsm4(r0, r1, r2, r3, pb);
                        bh[jp * 2][0] = r0; bh[jp * 2][1] = r1;
                        bh[jp * 2 + 1][0] = r2; bh[jp * 2 + 1][1] = r3;
                        ldsm4(r0, r1, r2, r3, pb + TILE_E);
                        bl[jp * 2][0] = r0; bl[jp * 2][1] = r1;
                        bl[jp * 2 + 1][0] = r2; bl[jp * 2 + 1][1] = r3;
                    }
                    #pragma unroll
                    for (int i = 0; i < 2; i++)
                        #pragma unroll
                        for (int j = 0; j < 4; j++) {
                            mma_f32acc(acch[i][j], ah[i], bh[j]);   // hi*hi
                            mma_f16acc(accc[i][j], ah[i], bl[j]);   // hi*lo'
                            mma_f16acc(accc[i][j], al[i], bh[j]);   // lo'*hi
                        }
                }
            };

            if (kEnd > 0) {
                const int NC = kEnd / CHUNK;          // 32 or 64
                // chunks 0,1: B possibly prefetched pre-barrier (empty-waits done)
                #pragma unroll
                for (int c = 0; c < 2; ++c) {
                    const int st = (int)(gf % NSTAGE);
                    if (!preB) {
                        if (gf >= NSTAGE) {
                            mbar_wait(mb + (NSTAGE + st) * 8, (pe >> st) & 1u);
                            pe ^= 1u << st;
                        }
                        loadB(st, c * CHUNK);
                    }
                    loadA(st, c * CHUNK);
                    cp_arrive_noinc(mb + st * 8);
                    gf++;
                }
                for (int c = 0; c < NC; ++c) {
                    const int sc = (int)(gc % NSTAGE);
                    mbar_wait(mb + sc * 8, (pf >> sc) & 1u);   // wait full[sc]
                    pf ^= 1u << sc;
                    if (c + 2 < NC) fill((c + 2) * CHUNK);     // overlaps compute below
                    compute(sc);
                    mbar_arrive(mb + (NSTAGE + sc) * 8);       // arrive empty[sc]
                    gc++;
                }
            }

            // ---- next step's B prefetch FIRST (overlaps epilogue + barrier) ----
            doPreB(s);

            // ---- epilogue: hh + corr/1024 + add -> tanh -> fp16 digit store ----
            {
                const size_t hoff = (size_t)(l * 2 + (t & 1)) * BH_;
                #pragma unroll
                for (int i = 0; i < 2; i++) {
                    const int m0 = bm + wm + i * 16 + (lane >> 2);
                    #pragma unroll
                    for (int j = 0; j < 4; j++) {
                        const int n0 = bn + wn + j * 8 + (lane & 3) * 2;
                        float a0, a1, a2, a3;
                        if (l == 0) {
                            const float* xp = XP0 + (size_t)t * BH_;
                            float2 u = *(const float2*)(xp + (size_t)m0 * H_ + n0);
                            float2 w = *(const float2*)(xp + (size_t)(m0 + 8) * H_ + n0);
                            a0 = u.x; a1 = u.y; a2 = w.x; a3 = w.y;
                        } else {
                            float2 u = *(const float2*)(b_ihr + (size_t)(l - 1) * H_ + n0);
                            a0 = u.x; a1 = u.y; a2 = u.x; a3 = u.y;
                        }
                        __half2 c01 = *(__half2*)&accc[i][j][0];
                        __half2 c23 = *(__half2*)&accc[i][j][1];
                        float v0 = tanhf(acch[i][j][0] + __half2float(c01.x) * INV_RS + a0);
                        float v1 = tanhf(acch[i][j][1] + __half2float(c01.y) * INV_RS + a1);
                        float v2 = tanhf(acch[i][j][2] + __half2float(c23.x) * INV_RS + a2);
                        float v3 = tanhf(acch[i][j][3] + __half2float(c23.y) * INV_RS + a3);

                        __half h0 = __float2half(v0), h1 = __float2half(v1);
                        __half h2 = __float2half(v2), h3 = __float2half(v3);
                        __half2 ph, pl;
                        ph.x = h0; ph.y = h1;
                        pl.x = __float2half((v0 - __half2float(h0)) * RSCALE);
                        pl.y = __float2half((v1 - __half2float(h1)) * RSCALE);
                        *(__half2*)(g_Hh + hoff + (size_t)m0 * H_ + n0) = ph;
                        *(__half2*)(g_Hl + hoff + (size_t)m0 * H_ + n0) = pl;
                        ph.x = h2; ph.y = h3;
                        pl.x = __float2half((v2 - __half2float(h2)) * RSCALE);
                        pl.y = __float2half((v3 - __half2float(h3)) * RSCALE);
                        *(__half2*)(g_Hh + hoff + (size_t)(m0 + 8) * H_ + n0) = ph;
                        *(__half2*)(g_Hl + hoff + (size_t)(m0 + 8) * H_ + n0) = pl;
                    }
                }
            }
        } else {
            // inactive this step: still issue next step's B prefetch
            doPreB(s);
        }

        grid_barrier((unsigned)(s + 1) * 128u);
    }
}

// ---------------------------------------------------------------------------
// Final FC: out[b] = (hi + lo/1024)[b,:] @ W_fc^T + b_fc
// ---------------------------------------------------------------------------
__global__ void fc_kernel(const __half* __restrict__ hh,
                          const __half* __restrict__ hl,
                          const float* __restrict__ w, const float* __restrict__ bfc,
                          float* __restrict__ out) {
    __shared__ float red[256];
    const size_t base = (size_t)blockIdx.x * H_;
    float s = 0.f;
    for (int j = threadIdx.x; j < H_; j += 256) {
        float hv = __half2float(hh[base + j]) + __half2float(hl[base + j]) * INV_RS;
        s = fmaf(hv, w[j], s);
    }
    red[threadIdx.x] = s;
    __syncthreads();
    for (int off = 128; off; off >>= 1) {
        if (threadIdx.x < off) red[threadIdx.x] += red[threadIdx.x + off];
        __syncthreads();
    }
    if (threadIdx.x == 0) out[blockIdx.x] = red[0] + bfc[0];
}

// ---------------------------------------------------------------------------
extern "C" void kernel_launch(void* const* d_in, const int* in_sizes, int n_in,
                              void* d_out, int out_size)
{
    const float* x      = (const float*)d_in[0];
    const float* W_ih0  = (const float*)d_in[1];
    const float* b_ih0  = (const float*)d_in[2];
    const float* W_ihr  = (const float*)d_in[3];
    const float* b_ihr  = (const float*)d_in[4];
    const float* W_hh   = (const float*)d_in[5];
    const float* W_fc   = (const float*)d_in[6];
    const float* b_fc   = (const float*)d_in[7];
    float* out = (float*)d_out;

    float *XT, *XP;
    __half *W0h, *W0l, *Wch, *Wcl, *Hh, *Hl;
    unsigned* bar;
    cudaGetSymbolAddress((void**)&XT,  g_XT);
    cudaGetSymbolAddress((void**)&XP,  g_XP);
    cudaGetSymbolAddress((void**)&W0h, g_W0h);
    cudaGetSymbolAddress((void**)&W0l, g_W0l);
    cudaGetSymbolAddress((void**)&Wch, g_Wch);
    cudaGetSymbolAddress((void**)&Wcl, g_Wcl);
    cudaGetSymbolAddress((void**)&Hh,  g_Hh);
    cudaGetSymbolAddress((void**)&Hl,  g_Hl);
    cudaGetSymbolAddress((void**)&bar, g_bar);

    static int smem_set = 0;
    if (!smem_set) {
        cudaFuncSetAttribute(wave_kernel, cudaFuncAttributeMaxDynamicSharedMemorySize,
                             DYN_SMEM);
        smem_set = 1;
    }

    cudaMemsetAsync(bar, 0, sizeof(unsigned));

    transpose_x<<<(T_ * B_ * (I_ / 4)) / 256, 256>>>(x, XT);

    // layer-0 input projection (fp32, K=64): XP = XT @ W_ih0^T + b_ih0
    gemm_nt<128, 64, 16, 8, 4><<<dim3(H_ / 64, (T_ * B_) / 128), 256>>>(
        XT, W_ih0, b_ih0, XP, T_ * B_, H_, I_);

    // merged weight hi/lo split (fp16 digits)
    {
        const size_t total = (size_t)H_ * H_ + (size_t)3 * H_ * K2_;
        prep_weights<<<(unsigned)(total / 256), 256>>>(W_hh, W_ihr, W0h, W0l, Wch, Wcl);
    }

    // wavefront over all layers/time
    wave_kernel<<<128, WTHREADS, DYN_SMEM>>>(XP, b_ihr);

    // final FC from h^{L-1}_{T-1} (parity (T-1)&1 = 1)
    fc_kernel<<<B_, 256>>>(Hh + (size_t)(3 * 2 + 1) * BH_,
                           Hl + (size_t)(3 * 2 + 1) * BH_, W_fc, b_fc, out);
}